// round 14
// baseline (speedup 1.0000x reference)
#include <cuda_runtime.h>
#include <cuda_fp16.h>
#include <math.h>
#include <stdint.h>

// Problem constants
#define BB 4
#define SS 2048
#define HH 16
#define DMODEL 1024
#define DK 64
#define MM (BB*SS)            // 8192

// ---------------- scratch (__device__ globals: allocation-guard safe) ------
__device__ __half g_hq[(size_t)MM*DMODEL];       // fp16 copies of raw inputs
__device__ __half g_hk[(size_t)MM*DMODEL];
__device__ __half g_hv[(size_t)MM*DMODEL];
__device__ __half g_hw[(size_t)4*DMODEL*DMODEL]; // Wq,Wk,Wv,Wo fp16
__device__ __half g_pq[(size_t)MM*DMODEL];       // projected q (scaled log2e/8)
__device__ __half g_pk[(size_t)MM*DMODEL];       // projected k
__device__ __half g_pv[(size_t)MM*DMODEL];       // projected v
__device__ __half g_attn[(size_t)MM*DMODEL];     // attention out [B,S,D] fp16

// ============================================================================
// PTX helpers — plain-ISA only (cp.async / ldmatrix / mma.sync). No tcgen05.
// ============================================================================
__device__ __forceinline__ uint32_t s2u(const void* p) {
    uint32_t a;
    asm("{ .reg .u64 t; cvta.to.shared.u64 t, %1; cvt.u32.u64 %0, t; }"
        : "=r"(a) : "l"(p));
    return a;
}
__device__ __forceinline__ void cp16(uint32_t dst, const void* src) {
    asm volatile("cp.async.cg.shared.global [%0], [%1], 16;" :: "r"(dst), "l"(src));
}
__device__ __forceinline__ void cp_commit() { asm volatile("cp.async.commit_group;"); }
__device__ __forceinline__ void cp_wait1()  { asm volatile("cp.async.wait_group 1;" ::: "memory"); }
__device__ __forceinline__ void cp_wait0()  { asm volatile("cp.async.wait_group 0;" ::: "memory"); }

__device__ __forceinline__ void ldsm4(uint32_t* r, uint32_t a) {
    asm volatile("ldmatrix.sync.aligned.m8n8.x4.shared.b16 {%0,%1,%2,%3}, [%4];"
                 : "=r"(r[0]), "=r"(r[1]), "=r"(r[2]), "=r"(r[3]) : "r"(a));
}
__device__ __forceinline__ void ldsm4t(uint32_t* r, uint32_t a) {
    asm volatile("ldmatrix.sync.aligned.m8n8.x4.trans.shared.b16 {%0,%1,%2,%3}, [%4];"
                 : "=r"(r[0]), "=r"(r[1]), "=r"(r[2]), "=r"(r[3]) : "r"(a));
}
__device__ __forceinline__ void mma16816(float* d, const uint32_t* a,
                                         uint32_t b0, uint32_t b1) {
    asm volatile(
        "mma.sync.aligned.m16n8k16.row.col.f32.f16.f16.f32 "
        "{%0,%1,%2,%3}, {%4,%5,%6,%7}, {%8,%9}, {%0,%1,%2,%3};"
        : "+f"(d[0]), "+f"(d[1]), "+f"(d[2]), "+f"(d[3])
        : "r"(a[0]), "r"(a[1]), "r"(a[2]), "r"(a[3]), "r"(b0), "r"(b1));
}
__device__ __forceinline__ uint32_t packh2(float x, float y) {
    __half2 h = __floats2half2_rn(x, y);
    return *reinterpret_cast<uint32_t*>(&h);
}

// ============================================================================
// fp32 -> fp16 conversions (2 launches)
// ============================================================================
__global__ __launch_bounds__(256)
void f2h_inputs(const float* __restrict__ s0, const float* __restrict__ s1,
                const float* __restrict__ s2,
                __half* __restrict__ d0, __half* __restrict__ d1,
                __half* __restrict__ d2, int n)
{
    const int z = blockIdx.z;
    const float* src = (z == 0) ? s0 : (z == 1) ? s1 : s2;
    __half*      dst = (z == 0) ? d0 : (z == 1) ? d1 : d2;
    int i = (blockIdx.x * blockDim.x + threadIdx.x) << 2;
    if (i >= n) return;
    float4 v = *(const float4*)(src + i);
    __half2* d = (__half2*)(dst + i);
    d[0] = __floats2half2_rn(v.x, v.y);
    d[1] = __floats2half2_rn(v.z, v.w);
}

__global__ __launch_bounds__(256)
void f2h_weights(const float* __restrict__ s0, const float* __restrict__ s1,
                 const float* __restrict__ s2, const float* __restrict__ s3,
                 __half* __restrict__ dst, int n)
{
    const int z = blockIdx.z;
    const float* src = (z == 0) ? s0 : (z == 1) ? s1 : (z == 2) ? s2 : s3;
    __half* d_ = dst + (size_t)z * n;
    int i = (blockIdx.x * blockDim.x + threadIdx.x) << 2;
    if (i >= n) return;
    float4 v = *(const float4*)(src + i);
    __half2* d = (__half2*)(d_ + i);
    d[0] = __floats2half2_rn(v.x, v.y);
    d[1] = __floats2half2_rn(v.z, v.w);
}

// ============================================================================
// HMMA GEMM core: CTA tile 256x128, K-step 32, 512 thr = 16 warps (4Mx4N),
// warp tile 64x32. 3-stage cp.async, ONE __syncthreads per k-step.
// smem pitch 80B/row; stage = A 20480B + B 10240B = 30720B; 3 stages = 92160B.
// grid = (1024/128, M/256[, z]).
// ============================================================================
#define GSTAGEB 30720
#define G_SMEM  (3*GSTAGEB)     // 92160

#define GEMM_ISSUE(Aptr, Wptr, st, k0)                                        \
    {   const uint32_t sob = (uint32_t)(st) * GSTAGEB;                        \
        _Pragma("unroll") for (int it = 0; it < 2; ++it) {                    \
            const int idx = tid + it * 512;                                   \
            const int r = idx >> 2, c = idx & 3;                              \
            cp16(sbase + sob + (uint32_t)(r * 80 + c * 16),                   \
                 (Aptr) + (size_t)(m0 + r) * DMODEL + (k0) + c * 8); }        \
        {   const int r = tid >> 2, c = tid & 3;                              \
            cp16(sbase + sob + 20480 + (uint32_t)(r * 80 + c * 16),           \
                 (Wptr) + (size_t)(n0 + r) * DMODEL + (k0) + c * 8); }        \
        cp_commit(); }

#define GEMM_BODY(Aptr, Wptr)                                                  \
    extern __shared__ __half gsm[];                                            \
    const uint32_t sbase = s2u(gsm);                                           \
    const int tid   = threadIdx.x;                                             \
    const int wid   = tid >> 5;                                                \
    const int lane  = tid & 31;                                                \
    const int warpM = wid >> 2;        /* 0..3 */                              \
    const int warpN = wid & 3;         /* 0..3 */                              \
    const int m0 = blockIdx.y * 256;                                           \
    const int n0 = blockIdx.x * 128;                                           \
    float acc[4][4][4];                                                        \
    _Pragma("unroll") for (int i = 0; i < 4; i++)                              \
    _Pragma("unroll") for (int j = 0; j < 4; j++)                              \
    _Pragma("unroll") for (int k = 0; k < 4; k++) acc[i][j][k] = 0.f;          \
    GEMM_ISSUE(Aptr, Wptr, 0, 0)                                               \
    GEMM_ISSUE(Aptr, Wptr, 1, 32)                                              \
    const int a_row_in = (lane & 15);                                          \
    const int a_k8     = (lane >> 4) << 4;                                     \
    const int b_nsub   = (lane & 7) + ((lane >> 4) & 1) * 8;                   \
    const int b_k8     = ((lane >> 3) & 1) << 4;                               \
    for (int s = 0; s < 32; ++s) {                                             \
        if (s < 30) cp_wait1(); else cp_wait0();                               \
        __syncthreads();                                                       \
        if (s + 2 < 32) GEMM_ISSUE(Aptr, Wptr, (s + 2) % 3, (s + 2) * 32)      \
        const uint32_t a_base = sbase + (uint32_t)(s % 3) * GSTAGEB;           \
        const uint32_t b_base = a_base + 20480;                                \
        _Pragma("unroll") for (int kk = 0; kk < 2; ++kk) {                     \
            uint32_t ar[4][4];                                                 \
            _Pragma("unroll") for (int mf = 0; mf < 4; ++mf) {                 \
                const int row = warpM * 64 + mf * 16 + a_row_in;               \
                ldsm4(ar[mf], a_base + (uint32_t)(row * 80 + kk * 32 + a_k8)); } \
            uint32_t br[2][4];                                                 \
            _Pragma("unroll") for (int nf2 = 0; nf2 < 2; ++nf2) {              \
                const int nrow = warpN * 32 + nf2 * 16 + b_nsub;               \
                ldsm4(br[nf2], b_base + (uint32_t)(nrow * 80 + kk * 32 + b_k8)); } \
            _Pragma("unroll") for (int mf = 0; mf < 4; ++mf)                   \
            _Pragma("unroll") for (int nf = 0; nf < 4; ++nf)                   \
                mma16816(acc[mf][nf], ar[mf],                                  \
                         br[nf >> 1][(nf & 1) * 2],                            \
                         br[nf >> 1][(nf & 1) * 2 + 1]); }                     \
    }                                                                          \
    const int rb = m0 + warpM * 64 + (lane >> 2);                              \
    const int cb = n0 + warpN * 32 + (lane & 3) * 2;

// ---- QKV projections (fused; fp16 out; q pre-scaled by log2e/sqrt(Dk)) -----
__global__ __launch_bounds__(512)
void gemm_qkv(const __half* __restrict__ hq, const __half* __restrict__ hk,
              const __half* __restrict__ hv, const __half* __restrict__ hw,
              const float* __restrict__ bq, const float* __restrict__ bk,
              const float* __restrict__ bv,
              __half* __restrict__ pq, __half* __restrict__ pk,
              __half* __restrict__ pv)
{
    const int z = blockIdx.z;
    const __half* A    = (z == 0) ? hq : (z == 1) ? hk : hv;
    const __half* W    = hw + (size_t)z * DMODEL * DMODEL;
    const float*  bias = (z == 0) ? bq : (z == 1) ? bk : bv;
    __half*       C    = (z == 0) ? pq : (z == 1) ? pk : pv;
    const float scale  = (z == 0) ? 0.125f * 1.44269504f : 1.0f;  // log2e/8

    GEMM_BODY(A, W)

#pragma unroll
    for (int nf = 0; nf < 4; ++nf) {
        const int c = cb + nf * 8;
        const float b0 = __ldg(bias + c), b1 = __ldg(bias + c + 1);
#pragma unroll
        for (int mf = 0; mf < 4; ++mf) {
            const int r = rb + mf * 16;
            __half2 h0 = __floats2half2_rn((acc[mf][nf][0] + b0) * scale,
                                           (acc[mf][nf][1] + b1) * scale);
            __half2 h1 = __floats2half2_rn((acc[mf][nf][2] + b0) * scale,
                                           (acc[mf][nf][3] + b1) * scale);
            *(__half2*)(C + (size_t)r * DMODEL + c)       = h0;
            *(__half2*)(C + (size_t)(r + 8) * DMODEL + c) = h1;
        }
    }
}

// ---- O projection (fp32 out) -----------------------------------------------
__global__ __launch_bounds__(512)
void gemm_hmma(const __half* __restrict__ Ain, const __half* __restrict__ Win,
               const float* __restrict__ bias, float* __restrict__ C)
{
    GEMM_BODY(Ain, Win)

#pragma unroll
    for (int nf = 0; nf < 4; ++nf) {
        const int c = cb + nf * 8;
        const float b0 = __ldg(bias + c), b1 = __ldg(bias + c + 1);
#pragma unroll
        for (int mf = 0; mf < 4; ++mf) {
            const int r = rb + mf * 16;
            *(float2*)(C + (size_t)r * DMODEL + c) =
                make_float2(acc[mf][nf][0] + b0, acc[mf][nf][1] + b1);
            *(float2*)(C + (size_t)(r + 8) * DMODEL + c) =
                make_float2(acc[mf][nf][2] + b0, acc[mf][nf][3] + b1);
        }
    }
}

// ============================================================================
// Tensor-core flash attention (causal). BM=128 (8 warps, 256 thr), BN=64.
// Scores arrive in log2 domain (q pre-scaled by log2e/8) -> exp2f softmax.
// Q frags in regs; P register-reuse; V via ldmatrix.trans; double-buffered
// cp.async K/V; ONE __syncthreads per KV tile. grid=(16, B*H), heavy first.
// ============================================================================
#define FP 72           // pitch in halves
#define FPB 144         // pitch in bytes
#define F_QB   18432    // Q bytes (128 rows)
#define F_KVB  9216     // one operand tile bytes (64 rows)
#define F_SMEM (F_QB + 4*F_KVB)   // 55296

__global__ __launch_bounds__(256)
void flash_tc(const __half* __restrict__ pq, const __half* __restrict__ pk,
              const __half* __restrict__ pv, __half* __restrict__ gout)
{
    extern __shared__ __half fsm[];
    const uint32_t uQ = s2u(fsm);

    const int tid  = threadIdx.x;
    const int lane = tid & 31;
    const int wid  = tid >> 5;
    const int bx   = (int)gridDim.x - 1 - (int)blockIdx.x;  // heavy first
    const int bh   = blockIdx.y;
    const int b_   = bh >> 4;
    const int h    = bh & (HH - 1);
    const int q0   = bx * 128;
    const int nt   = 2 * bx + 2;           // KV tiles
    const size_t rowbase = (size_t)b_ * SS;
    const int coloff = h * DK;

    // Q tile load (128 rows; group 0)
    {
        const __half* qg = pq + (rowbase + q0) * DMODEL + coloff;
#pragma unroll
        for (int it = 0; it < 4; ++it) {
            const int idx = tid + it * 256;
            const int r = idx >> 3, c = idx & 7;
            cp16(uQ + (uint32_t)(r * FPB + c * 16), qg + (size_t)r * DMODEL + c * 8);
        }
        cp_commit();
    }

#define LOAD_KV(kt_, buf_)                                                     \
    {   const __half* kg = pk + (rowbase + (kt_) * 64) * DMODEL + coloff;      \
        const __half* vg = pv + (rowbase + (kt_) * 64) * DMODEL + coloff;      \
        const uint32_t kb = uQ + F_QB + (uint32_t)(buf_) * (2 * F_KVB);        \
        _Pragma("unroll") for (int it = 0; it < 2; ++it) {                     \
            const int idx = tid + it * 256;                                    \
            const int r = idx >> 3, c = idx & 7;                               \
            const uint32_t so = (uint32_t)(r * FPB + c * 16);                  \
            cp16(kb + so,         kg + (size_t)r * DMODEL + c * 8);            \
            cp16(kb + F_KVB + so, vg + (size_t)r * DMODEL + c * 8); }          \
        cp_commit(); }

    LOAD_KV(0, 0)
    cp_wait1();          // Q done (KV0 may be in flight)
    __syncthreads();

    // Q fragments -> registers (once)
    const int arow = lane & 15;
    const int ak8  = (lane >> 4) << 4;   // bytes
    uint32_t qf[4][4];
#pragma unroll
    for (int j = 0; j < 4; ++j)
        ldsm4(qf[j], uQ + (uint32_t)((wid * 16 + arow) * FPB + j * 32 + ak8));

    float oacc[8][4];
#pragma unroll
    for (int nf = 0; nf < 8; ++nf)
#pragma unroll
        for (int k = 0; k < 4; ++k) oacc[nf][k] = 0.f;
    float m0 = -1e30f, m1 = -1e30f, l0 = 0.f, l1 = 0.f;

    const int lr0 = wid * 16 + (lane >> 2);   // local query row of regs 0,1
    const int lr1 = lr0 + 8;                  // regs 2,3

    for (int kt = 0; kt < nt; ++kt) {
        cp_wait0();                 // KV kt landed
        __syncthreads();            // publish; frees old buffer
        if (kt + 1 < nt) LOAD_KV(kt + 1, (kt + 1) & 1)

        const uint32_t ukb = uQ + F_QB + (uint32_t)(kt & 1) * (2 * F_KVB);
        const uint32_t uvb = ukb + F_KVB;

        // ---- S = Q K^T (log2 domain) ----
        float s[8][4];
#pragma unroll
        for (int nf = 0; nf < 8; ++nf)
#pragma unroll
            for (int k = 0; k < 4; ++k) s[nf][k] = 0.f;

#pragma unroll
        for (int j = 0; j < 4; ++j) {
#pragma unroll
            for (int nb = 0; nb < 4; ++nb) {
                uint32_t br[4];
                ldsm4(br, ukb + (uint32_t)((nb * 16 + arow) * FPB + j * 32 + ak8));
                mma16816(s[2 * nb],     qf[j], br[0], br[2]);
                mma16816(s[2 * nb + 1], qf[j], br[1], br[3]);
            }
        }

        // ---- causal mask (two partial tiles per CTA) ----
        if (kt >= 2 * bx) {
            const int off = q0 - kt * 64;   // 0 or -64
#pragma unroll
            for (int nf = 0; nf < 8; ++nf) {
                const int kc0 = nf * 8 + (lane & 3) * 2;
                const int kc1 = kc0 + 1;
                if (kc0 > lr0 + off) s[nf][0] = -1e30f;
                if (kc1 > lr0 + off) s[nf][1] = -1e30f;
                if (kc0 > lr1 + off) s[nf][2] = -1e30f;
                if (kc1 > lr1 + off) s[nf][3] = -1e30f;
            }
        }

        // ---- online softmax (exp2, fragment layout) ----
        float mx0 = -1e30f, mx1 = -1e30f;
#pragma unroll
        for (int nf = 0; nf < 8; ++nf) {
            mx0 = fmaxf(mx0, fmaxf(s[nf][0], s[nf][1]));
            mx1 = fmaxf(mx1, fmaxf(s[nf][2], s[nf][3]));
        }
        mx0 = fmaxf(mx0, __shfl_xor_sync(0xffffffffu, mx0, 1));
        mx0 = fmaxf(mx0, __shfl_xor_sync(0xffffffffu, mx0, 2));
        mx1 = fmaxf(mx1, __shfl_xor_sync(0xffffffffu, mx1, 1));
        mx1 = fmaxf(mx1, __shfl_xor_sync(0xffffffffu, mx1, 2));

        const float mn0 = fmaxf(m0, mx0);
        const float mn1 = fmaxf(m1, mx1);
        const float a0 = exp2f(m0 - mn0);
        const float a1 = exp2f(m1 - mn1);
        float sum0 = 0.f, sum1 = 0.f;
#pragma unroll
        for (int nf = 0; nf < 8; ++nf) {
            s[nf][0] = exp2f(s[nf][0] - mn0);
            s[nf][1] = exp2f(s[nf][1] - mn0);
            s[nf][2] = exp2f(s[nf][2] - mn1);
            s[nf][3] = exp2f(s[nf][3] - mn1);
            sum0 += s[nf][0] + s[nf][1];
            sum1 += s[nf][2] + s[nf][3];
        }
        sum0 += __shfl_xor_sync(0xffffffffu, sum0, 1);
        sum0 += __shfl_xor_sync(0xffffffffu, sum0, 2);
        sum1 += __shfl_xor_sync(0xffffffffu, sum1, 1);
        sum1 += __shfl_xor_sync(0xffffffffu, sum1, 2);
        l0 = l0 * a0 + sum0;  m0 = mn0;
        l1 = l1 * a1 + sum1;  m1 = mn1;
#pragma unroll
        for (int nf = 0; nf < 8; ++nf) {
            oacc[nf][0] *= a0; oacc[nf][1] *= a0;
            oacc[nf][2] *= a1; oacc[nf][3] *= a1;
        }

        // ---- P (fp16 A-frags, register reuse) ----
        uint32_t pa[4][4];
#pragma unroll
        for (int j = 0; j < 4; ++j) {
            pa[j][0] = packh2(s[2 * j][0],     s[2 * j][1]);
            pa[j][1] = packh2(s[2 * j][2],     s[2 * j][3]);
            pa[j][2] = packh2(s[2 * j + 1][0], s[2 * j + 1][1]);
            pa[j][3] = packh2(s[2 * j + 1][2], s[2 * j + 1][3]);
        }

        // ---- O += P V  (V via ldmatrix.trans) ----
#pragma unroll
        for (int j = 0; j < 4; ++j) {
#pragma unroll
            for (int db = 0; db < 4; ++db) {
                uint32_t bv[4];
                ldsm4t(bv, uvb + (uint32_t)((j * 16 + arow) * FPB
                                            + (db * 16 + (lane >> 4) * 8) * 2));
                mma16816(oacc[2 * db],     pa[j], bv[0], bv[1]);
                mma16816(oacc[2 * db + 1], pa[j], bv[2], bv[3]);
            }
        }
    }

    // ---- epilogue: normalize, write fp16 [B,S,D] ----
    const float inv0 = 1.0f / l0;
    const float inv1 = 1.0f / l1;
    const size_t gr0 = rowbase + q0 + (size_t)lr0;
    const size_t gr1 = gr0 + 8;
#pragma unroll
    for (int nf = 0; nf < 8; ++nf) {
        const int col = coloff + nf * 8 + (lane & 3) * 2;
        *(__half2*)(gout + gr0 * DMODEL + col) =
            __floats2half2_rn(oacc[nf][0] * inv0, oacc[nf][1] * inv0);
        *(__half2*)(gout + gr1 * DMODEL + col) =
            __floats2half2_rn(oacc[nf][2] * inv1, oacc[nf][3] * inv1);
    }
#undef LOAD_KV
}

// ============================================================================
// launch
// ============================================================================
extern "C" void kernel_launch(void* const* d_in, const int* in_sizes, int n_in,
                              void* d_out, int out_size)
{
    const float* Q   = (const float*)d_in[0];
    const float* K   = (const float*)d_in[1];
    const float* V   = (const float*)d_in[2];
    // d_in[3] = mask (causal tril; handled analytically)
    const float* W_q = (const float*)d_in[4];
    const float* b_q = (const float*)d_in[5];
    const float* W_k = (const float*)d_in[6];
    const float* b_k = (const float*)d_in[7];
    const float* W_v = (const float*)d_in[8];
    const float* b_v = (const float*)d_in[9];
    const float* W_o = (const float*)d_in[10];
    const float* b_o = (const float*)d_in[11];
    float* out = (float*)d_out;

    __half *hq, *hk, *hv, *hw, *pq, *pk, *pv, *gattn;
    cudaGetSymbolAddress((void**)&hq,    g_hq);
    cudaGetSymbolAddress((void**)&hk,    g_hk);
    cudaGetSymbolAddress((void**)&hv,    g_hv);
    cudaGetSymbolAddress((void**)&hw,    g_hw);
    cudaGetSymbolAddress((void**)&pq,    g_pq);
    cudaGetSymbolAddress((void**)&pk,    g_pk);
    cudaGetSymbolAddress((void**)&pv,    g_pv);
    cudaGetSymbolAddress((void**)&gattn, g_attn);

    cudaFuncSetAttribute(gemm_qkv,
                         cudaFuncAttributeMaxDynamicSharedMemorySize, G_SMEM);
    cudaFuncSetAttribute(gemm_hmma,
                         cudaFuncAttributeMaxDynamicSharedMemorySize, G_SMEM);
    cudaFuncSetAttribute(flash_tc,
                         cudaFuncAttributeMaxDynamicSharedMemorySize, F_SMEM);

    const int nBig = MM * DMODEL;          // 8,388,608
    const int nW   = DMODEL * DMODEL;      // 1,048,576

    f2h_inputs<<<dim3(nBig / 4 / 256, 1, 3), 256>>>(Q, K, V, hq, hk, hv, nBig);
    f2h_weights<<<dim3(nW / 4 / 256, 1, 4), 256>>>(W_q, W_k, W_v, W_o, hw, nW);

    // fused QKV projections (fp16 out; q pre-scaled by log2e/sqrt(Dk))
    gemm_qkv<<<dim3(DMODEL / 128, MM / 256, 3), 512, G_SMEM>>>(
        hq, hk, hv, hw, b_q, b_k, b_v, pq, pk, pv);

    // tensor-core causal flash attention (BM=128, exp2 softmax)
    flash_tc<<<dim3(SS / 128, BB * HH), 256, F_SMEM>>>(pq, pk, pv, gattn);

    // O projection (fp32 out)
    gemm_hmma<<<dim3(DMODEL / 128, MM / 256), 512, G_SMEM>>>(
        gattn, hw + 3 * (size_t)nW, b_o, out);
}

// round 15
// speedup vs baseline: 1.0968x; 1.0968x over previous
#include <cuda_runtime.h>
#include <cuda_fp16.h>
#include <math.h>
#include <stdint.h>

// Problem constants
#define BB 4
#define SS 2048
#define HH 16
#define DMODEL 1024
#define DK 64
#define MM (BB*SS)            // 8192

// ---------------- scratch (__device__ globals: allocation-guard safe) ------
__device__ __half g_hq[(size_t)MM*DMODEL];       // fp16 copies of raw inputs
__device__ __half g_hk[(size_t)MM*DMODEL];
__device__ __half g_hv[(size_t)MM*DMODEL];
__device__ __half g_hw[(size_t)4*DMODEL*DMODEL]; // Wq,Wk,Wv,Wo fp16
__device__ __half g_pq[(size_t)MM*DMODEL];       // projected q (scaled log2e/8)
__device__ __half g_pk[(size_t)MM*DMODEL];       // projected k
__device__ __half g_pv[(size_t)MM*DMODEL];       // projected v
__device__ __half g_attn[(size_t)MM*DMODEL];     // attention out [B,S,D] fp16

// ============================================================================
// PTX helpers — plain-ISA only (cp.async / ldmatrix / mma.sync). No tcgen05.
// ============================================================================
__device__ __forceinline__ uint32_t s2u(const void* p) {
    uint32_t a;
    asm("{ .reg .u64 t; cvta.to.shared.u64 t, %1; cvt.u32.u64 %0, t; }"
        : "=r"(a) : "l"(p));
    return a;
}
__device__ __forceinline__ void cp16(uint32_t dst, const void* src) {
    asm volatile("cp.async.cg.shared.global [%0], [%1], 16;" :: "r"(dst), "l"(src));
}
__device__ __forceinline__ void cp_commit() { asm volatile("cp.async.commit_group;"); }
__device__ __forceinline__ void cp_wait1()  { asm volatile("cp.async.wait_group 1;" ::: "memory"); }
__device__ __forceinline__ void cp_wait0()  { asm volatile("cp.async.wait_group 0;" ::: "memory"); }

__device__ __forceinline__ void ldsm4(uint32_t* r, uint32_t a) {
    asm volatile("ldmatrix.sync.aligned.m8n8.x4.shared.b16 {%0,%1,%2,%3}, [%4];"
                 : "=r"(r[0]), "=r"(r[1]), "=r"(r[2]), "=r"(r[3]) : "r"(a));
}
__device__ __forceinline__ void ldsm4t(uint32_t* r, uint32_t a) {
    asm volatile("ldmatrix.sync.aligned.m8n8.x4.trans.shared.b16 {%0,%1,%2,%3}, [%4];"
                 : "=r"(r[0]), "=r"(r[1]), "=r"(r[2]), "=r"(r[3]) : "r"(a));
}
__device__ __forceinline__ void mma16816(float* d, const uint32_t* a,
                                         uint32_t b0, uint32_t b1) {
    asm volatile(
        "mma.sync.aligned.m16n8k16.row.col.f32.f16.f16.f32 "
        "{%0,%1,%2,%3}, {%4,%5,%6,%7}, {%8,%9}, {%0,%1,%2,%3};"
        : "+f"(d[0]), "+f"(d[1]), "+f"(d[2]), "+f"(d[3])
        : "r"(a[0]), "r"(a[1]), "r"(a[2]), "r"(a[3]), "r"(b0), "r"(b1));
}
__device__ __forceinline__ uint32_t packh2(float x, float y) {
    __half2 h = __floats2half2_rn(x, y);
    return *reinterpret_cast<uint32_t*>(&h);
}

// ============================================================================
// fp32 -> fp16 conversions (2 launches)
// ============================================================================
__global__ __launch_bounds__(256)
void f2h_inputs(const float* __restrict__ s0, const float* __restrict__ s1,
                const float* __restrict__ s2,
                __half* __restrict__ d0, __half* __restrict__ d1,
                __half* __restrict__ d2, int n)
{
    const int z = blockIdx.z;
    const float* src = (z == 0) ? s0 : (z == 1) ? s1 : s2;
    __half*      dst = (z == 0) ? d0 : (z == 1) ? d1 : d2;
    int i = (blockIdx.x * blockDim.x + threadIdx.x) << 2;
    if (i >= n) return;
    float4 v = *(const float4*)(src + i);
    __half2* d = (__half2*)(dst + i);
    d[0] = __floats2half2_rn(v.x, v.y);
    d[1] = __floats2half2_rn(v.z, v.w);
}

__global__ __launch_bounds__(256)
void f2h_weights(const float* __restrict__ s0, const float* __restrict__ s1,
                 const float* __restrict__ s2, const float* __restrict__ s3,
                 __half* __restrict__ dst, int n)
{
    const int z = blockIdx.z;
    const float* src = (z == 0) ? s0 : (z == 1) ? s1 : (z == 2) ? s2 : s3;
    __half* d_ = dst + (size_t)z * n;
    int i = (blockIdx.x * blockDim.x + threadIdx.x) << 2;
    if (i >= n) return;
    float4 v = *(const float4*)(src + i);
    __half2* d = (__half2*)(d_ + i);
    d[0] = __floats2half2_rn(v.x, v.y);
    d[1] = __floats2half2_rn(v.z, v.w);
}

// ============================================================================
// HMMA GEMM core (R12 config — fastest measured): CTA 128x128, K-step 32,
// 256 thr = 8 warps (2Mx4N), warp tile 64x32, 2-stage STATIC smem cp.async
// double buffer, pitch 80B. grid = (1024/128, M/128[, z]).
// ============================================================================
#define GP 40
#define GTILE (128*GP)

#define GEMM_BODY(Aptr, Wptr)                                                  \
    __shared__ __half As[2][GTILE];                                            \
    __shared__ __half Bs[2][GTILE];                                            \
    const int tid   = threadIdx.x;                                             \
    const int wid   = tid >> 5;                                                \
    const int lane  = tid & 31;                                                \
    const int warpM = wid >> 2;                                                \
    const int warpN = wid & 3;                                                 \
    const int m0 = blockIdx.y * 128;                                            \
    const int n0 = blockIdx.x * 128;                                            \
    const uint32_t sA = s2u(As);                                                \
    const uint32_t sB = s2u(Bs);                                                \
    float acc[4][4][4];                                                         \
    _Pragma("unroll") for (int i = 0; i < 4; i++)                               \
    _Pragma("unroll") for (int j = 0; j < 4; j++)                               \
    _Pragma("unroll") for (int k = 0; k < 4; k++) acc[i][j][k] = 0.f;           \
    const int lr0 = tid >> 2;                                                   \
    const int lc0 = tid & 3;                                                    \
    {   _Pragma("unroll") for (int it = 0; it < 2; ++it) {                      \
            const int r = lr0 + it * 64;                                        \
            const uint32_t so = (uint32_t)(r * 80 + lc0 * 16);                  \
            cp16(sA + so, (Aptr) + (size_t)(m0 + r) * DMODEL + lc0 * 8);        \
            cp16(sB + so, (Wptr) + (size_t)(n0 + r) * DMODEL + lc0 * 8); }      \
        cp_commit(); }                                                          \
    const int a_row_in = (lane & 15);                                           \
    const int a_k8     = (lane >> 4) << 4;                                      \
    const int b_nsub   = (lane & 7) + ((lane >> 4) & 1) * 8;                    \
    const int b_k8     = ((lane >> 3) & 1) << 4;                                \
    for (int s = 0; s < 32; ++s) {                                              \
        if (s + 1 < 32) {                                                       \
            const int k0n = (s + 1) * 32;                                       \
            const uint32_t bo = (uint32_t)((s + 1) & 1) * (GTILE * 2);          \
            _Pragma("unroll") for (int it = 0; it < 2; ++it) {                  \
                const int r = lr0 + it * 64;                                    \
                const uint32_t so = bo + (uint32_t)(r * 80 + lc0 * 16);         \
                cp16(sA + so, (Aptr) + (size_t)(m0 + r) * DMODEL + k0n + lc0 * 8); \
                cp16(sB + so, (Wptr) + (size_t)(n0 + r) * DMODEL + k0n + lc0 * 8); } \
            cp_commit(); cp_wait1();                                            \
        } else cp_wait0();                                                      \
        __syncthreads();                                                        \
        const uint32_t a_base = sA + (uint32_t)(s & 1) * (GTILE * 2);           \
        const uint32_t b_base = sB + (uint32_t)(s & 1) * (GTILE * 2);           \
        _Pragma("unroll") for (int kk = 0; kk < 2; ++kk) {                      \
            uint32_t ar[4][4];                                                  \
            _Pragma("unroll") for (int mf = 0; mf < 4; ++mf) {                  \
                const int row = warpM * 64 + mf * 16 + a_row_in;                \
                ldsm4(ar[mf], a_base + (uint32_t)(row * 80 + kk * 32 + a_k8)); } \
            uint32_t br[2][4];                                                  \
            _Pragma("unroll") for (int nf2 = 0; nf2 < 2; ++nf2) {               \
                const int nrow = warpN * 32 + nf2 * 16 + b_nsub;                \
                ldsm4(br[nf2], b_base + (uint32_t)(nrow * 80 + kk * 32 + b_k8)); } \
            _Pragma("unroll") for (int mf = 0; mf < 4; ++mf)                    \
            _Pragma("unroll") for (int nf = 0; nf < 4; ++nf)                    \
                mma16816(acc[mf][nf], ar[mf],                                   \
                         br[nf >> 1][(nf & 1) * 2],                             \
                         br[nf >> 1][(nf & 1) * 2 + 1]); }                      \
        __syncthreads(); }                                                      \
    const int rb = m0 + warpM * 64 + (lane >> 2);                               \
    const int cb = n0 + warpN * 32 + (lane & 3) * 2;

// ---- QKV projections (fused; fp16 out; q pre-scaled by log2e/sqrt(Dk)) -----
__global__ __launch_bounds__(256)
void gemm_qkv(const __half* __restrict__ hq, const __half* __restrict__ hk,
              const __half* __restrict__ hv, const __half* __restrict__ hw,
              const float* __restrict__ bq, const float* __restrict__ bk,
              const float* __restrict__ bv,
              __half* __restrict__ pq, __half* __restrict__ pk,
              __half* __restrict__ pv)
{
    const int z = blockIdx.z;
    const __half* A    = (z == 0) ? hq : (z == 1) ? hk : hv;
    const __half* W    = hw + (size_t)z * DMODEL * DMODEL;
    const float*  bias = (z == 0) ? bq : (z == 1) ? bk : bv;
    __half*       C    = (z == 0) ? pq : (z == 1) ? pk : pv;
    const float scale  = (z == 0) ? 0.125f * 1.44269504f : 1.0f;  // log2e/8

    GEMM_BODY(A, W)

#pragma unroll
    for (int nf = 0; nf < 4; ++nf) {
        const int c = cb + nf * 8;
        const float b0 = __ldg(bias + c), b1 = __ldg(bias + c + 1);
#pragma unroll
        for (int mf = 0; mf < 4; ++mf) {
            const int r = rb + mf * 16;
            __half2 h0 = __floats2half2_rn((acc[mf][nf][0] + b0) * scale,
                                           (acc[mf][nf][1] + b1) * scale);
            __half2 h1 = __floats2half2_rn((acc[mf][nf][2] + b0) * scale,
                                           (acc[mf][nf][3] + b1) * scale);
            *(__half2*)(C + (size_t)r * DMODEL + c)       = h0;
            *(__half2*)(C + (size_t)(r + 8) * DMODEL + c) = h1;
        }
    }
}

// ---- O projection (fp32 out) -----------------------------------------------
__global__ __launch_bounds__(256)
void gemm_hmma(const __half* __restrict__ Ain, const __half* __restrict__ Win,
               const float* __restrict__ bias, float* __restrict__ C)
{
    GEMM_BODY(Ain, Win)

#pragma unroll
    for (int nf = 0; nf < 4; ++nf) {
        const int c = cb + nf * 8;
        const float b0 = __ldg(bias + c), b1 = __ldg(bias + c + 1);
#pragma unroll
        for (int mf = 0; mf < 4; ++mf) {
            const int r = rb + mf * 16;
            *(float2*)(C + (size_t)r * DMODEL + c) =
                make_float2(acc[mf][nf][0] + b0, acc[mf][nf][1] + b1);
            *(float2*)(C + (size_t)(r + 8) * DMODEL + c) =
                make_float2(acc[mf][nf][2] + b0, acc[mf][nf][3] + b1);
        }
    }
}

// ============================================================================
// Tensor-core flash attention (R14 config — fastest measured, 156us).
// BM=128 (8 warps, 256 thr), BN=64, exp2-domain softmax. Q frags in regs;
// P register-reuse; V via ldmatrix.trans; double-buffered cp.async K/V;
// ONE __syncthreads per KV tile. grid=(16, B*H), heavy tiles first.
// ============================================================================
#define FP 72           // pitch in halves
#define FPB 144         // pitch in bytes
#define F_QB   18432    // Q bytes (128 rows)
#define F_KVB  9216     // one operand tile bytes (64 rows)
#define F_SMEM (F_QB + 4*F_KVB)   // 55296

__global__ __launch_bounds__(256)
void flash_tc(const __half* __restrict__ pq, const __half* __restrict__ pk,
              const __half* __restrict__ pv, __half* __restrict__ gout)
{
    extern __shared__ __half fsm[];
    const uint32_t uQ = s2u(fsm);

    const int tid  = threadIdx.x;
    const int lane = tid & 31;
    const int wid  = tid >> 5;
    const int bx   = (int)gridDim.x - 1 - (int)blockIdx.x;  // heavy first
    const int bh   = blockIdx.y;
    const int b_   = bh >> 4;
    const int h    = bh & (HH - 1);
    const int q0   = bx * 128;
    const int nt   = 2 * bx + 2;           // KV tiles
    const size_t rowbase = (size_t)b_ * SS;
    const int coloff = h * DK;

    // Q tile load (128 rows; group 0)
    {
        const __half* qg = pq + (rowbase + q0) * DMODEL + coloff;
#pragma unroll
        for (int it = 0; it < 4; ++it) {
            const int idx = tid + it * 256;
            const int r = idx >> 3, c = idx & 7;
            cp16(uQ + (uint32_t)(r * FPB + c * 16), qg + (size_t)r * DMODEL + c * 8);
        }
        cp_commit();
    }

#define LOAD_KV(kt_, buf_)                                                     \
    {   const __half* kg = pk + (rowbase + (kt_) * 64) * DMODEL + coloff;      \
        const __half* vg = pv + (rowbase + (kt_) * 64) * DMODEL + coloff;      \
        const uint32_t kb = uQ + F_QB + (uint32_t)(buf_) * (2 * F_KVB);        \
        _Pragma("unroll") for (int it = 0; it < 2; ++it) {                     \
            const int idx = tid + it * 256;                                    \
            const int r = idx >> 3, c = idx & 7;                               \
            const uint32_t so = (uint32_t)(r * FPB + c * 16);                  \
            cp16(kb + so,         kg + (size_t)r * DMODEL + c * 8);            \
            cp16(kb + F_KVB + so, vg + (size_t)r * DMODEL + c * 8); }          \
        cp_commit(); }

    LOAD_KV(0, 0)
    cp_wait1();          // Q done (KV0 may be in flight)
    __syncthreads();

    // Q fragments -> registers (once)
    const int arow = lane & 15;
    const int ak8  = (lane >> 4) << 4;   // bytes
    uint32_t qf[4][4];
#pragma unroll
    for (int j = 0; j < 4; ++j)
        ldsm4(qf[j], uQ + (uint32_t)((wid * 16 + arow) * FPB + j * 32 + ak8));

    float oacc[8][4];
#pragma unroll
    for (int nf = 0; nf < 8; ++nf)
#pragma unroll
        for (int k = 0; k < 4; ++k) oacc[nf][k] = 0.f;
    float m0 = -1e30f, m1 = -1e30f, l0 = 0.f, l1 = 0.f;

    const int lr0 = wid * 16 + (lane >> 2);   // local query row of regs 0,1
    const int lr1 = lr0 + 8;                  // regs 2,3

    for (int kt = 0; kt < nt; ++kt) {
        cp_wait0();                 // KV kt landed
        __syncthreads();            // publish; frees old buffer
        if (kt + 1 < nt) LOAD_KV(kt + 1, (kt + 1) & 1)

        const uint32_t ukb = uQ + F_QB + (uint32_t)(kt & 1) * (2 * F_KVB);
        const uint32_t uvb = ukb + F_KVB;

        // ---- S = Q K^T (log2 domain) ----
        float s[8][4];
#pragma unroll
        for (int nf = 0; nf < 8; ++nf)
#pragma unroll
            for (int k = 0; k < 4; ++k) s[nf][k] = 0.f;

#pragma unroll
        for (int j = 0; j < 4; ++j) {
#pragma unroll
            for (int nb = 0; nb < 4; ++nb) {
                uint32_t br[4];
                ldsm4(br, ukb + (uint32_t)((nb * 16 + arow) * FPB + j * 32 + ak8));
                mma16816(s[2 * nb],     qf[j], br[0], br[2]);
                mma16816(s[2 * nb + 1], qf[j], br[1], br[3]);
            }
        }

        // ---- causal mask (two partial tiles per CTA) ----
        if (kt >= 2 * bx) {
            const int off = q0 - kt * 64;   // 0 or -64
#pragma unroll
            for (int nf = 0; nf < 8; ++nf) {
                const int kc0 = nf * 8 + (lane & 3) * 2;
                const int kc1 = kc0 + 1;
                if (kc0 > lr0 + off) s[nf][0] = -1e30f;
                if (kc1 > lr0 + off) s[nf][1] = -1e30f;
                if (kc0 > lr1 + off) s[nf][2] = -1e30f;
                if (kc1 > lr1 + off) s[nf][3] = -1e30f;
            }
        }

        // ---- online softmax (exp2, fragment layout) ----
        float mx0 = -1e30f, mx1 = -1e30f;
#pragma unroll
        for (int nf = 0; nf < 8; ++nf) {
            mx0 = fmaxf(mx0, fmaxf(s[nf][0], s[nf][1]));
            mx1 = fmaxf(mx1, fmaxf(s[nf][2], s[nf][3]));
        }
        mx0 = fmaxf(mx0, __shfl_xor_sync(0xffffffffu, mx0, 1));
        mx0 = fmaxf(mx0, __shfl_xor_sync(0xffffffffu, mx0, 2));
        mx1 = fmaxf(mx1, __shfl_xor_sync(0xffffffffu, mx1, 1));
        mx1 = fmaxf(mx1, __shfl_xor_sync(0xffffffffu, mx1, 2));

        const float mn0 = fmaxf(m0, mx0);
        const float mn1 = fmaxf(m1, mx1);
        const float a0 = exp2f(m0 - mn0);
        const float a1 = exp2f(m1 - mn1);
        float sum0 = 0.f, sum1 = 0.f;
#pragma unroll
        for (int nf = 0; nf < 8; ++nf) {
            s[nf][0] = exp2f(s[nf][0] - mn0);
            s[nf][1] = exp2f(s[nf][1] - mn0);
            s[nf][2] = exp2f(s[nf][2] - mn1);
            s[nf][3] = exp2f(s[nf][3] - mn1);
            sum0 += s[nf][0] + s[nf][1];
            sum1 += s[nf][2] + s[nf][3];
        }
        sum0 += __shfl_xor_sync(0xffffffffu, sum0, 1);
        sum0 += __shfl_xor_sync(0xffffffffu, sum0, 2);
        sum1 += __shfl_xor_sync(0xffffffffu, sum1, 1);
        sum1 += __shfl_xor_sync(0xffffffffu, sum1, 2);
        l0 = l0 * a0 + sum0;  m0 = mn0;
        l1 = l1 * a1 + sum1;  m1 = mn1;
#pragma unroll
        for (int nf = 0; nf < 8; ++nf) {
            oacc[nf][0] *= a0; oacc[nf][1] *= a0;
            oacc[nf][2] *= a1; oacc[nf][3] *= a1;
        }

        // ---- P (fp16 A-frags, register reuse) ----
        uint32_t pa[4][4];
#pragma unroll
        for (int j = 0; j < 4; ++j) {
            pa[j][0] = packh2(s[2 * j][0],     s[2 * j][1]);
            pa[j][1] = packh2(s[2 * j][2],     s[2 * j][3]);
            pa[j][2] = packh2(s[2 * j + 1][0], s[2 * j + 1][1]);
            pa[j][3] = packh2(s[2 * j + 1][2], s[2 * j + 1][3]);
        }

        // ---- O += P V  (V via ldmatrix.trans) ----
#pragma unroll
        for (int j = 0; j < 4; ++j) {
#pragma unroll
            for (int db = 0; db < 4; ++db) {
                uint32_t bv[4];
                ldsm4t(bv, uvb + (uint32_t)((j * 16 + arow) * FPB
                                            + (db * 16 + (lane >> 4) * 8) * 2));
                mma16816(oacc[2 * db],     pa[j], bv[0], bv[1]);
                mma16816(oacc[2 * db + 1], pa[j], bv[2], bv[3]);
            }
        }
    }

    // ---- epilogue: normalize, write fp16 [B,S,D] ----
    const float inv0 = 1.0f / l0;
    const float inv1 = 1.0f / l1;
    const size_t gr0 = rowbase + q0 + (size_t)lr0;
    const size_t gr1 = gr0 + 8;
#pragma unroll
    for (int nf = 0; nf < 8; ++nf) {
        const int col = coloff + nf * 8 + (lane & 3) * 2;
        *(__half2*)(gout + gr0 * DMODEL + col) =
            __floats2half2_rn(oacc[nf][0] * inv0, oacc[nf][1] * inv0);
        *(__half2*)(gout + gr1 * DMODEL + col) =
            __floats2half2_rn(oacc[nf][2] * inv1, oacc[nf][3] * inv1);
    }
#undef LOAD_KV
}

// ============================================================================
// launch
// ============================================================================
extern "C" void kernel_launch(void* const* d_in, const int* in_sizes, int n_in,
                              void* d_out, int out_size)
{
    const float* Q   = (const float*)d_in[0];
    const float* K   = (const float*)d_in[1];
    const float* V   = (const float*)d_in[2];
    // d_in[3] = mask (causal tril; handled analytically)
    const float* W_q = (const float*)d_in[4];
    const float* b_q = (const float*)d_in[5];
    const float* W_k = (const float*)d_in[6];
    const float* b_k = (const float*)d_in[7];
    const float* W_v = (const float*)d_in[8];
    const float* b_v = (const float*)d_in[9];
    const float* W_o = (const float*)d_in[10];
    const float* b_o = (const float*)d_in[11];
    float* out = (float*)d_out;

    __half *hq, *hk, *hv, *hw, *pq, *pk, *pv, *gattn;
    cudaGetSymbolAddress((void**)&hq,    g_hq);
    cudaGetSymbolAddress((void**)&hk,    g_hk);
    cudaGetSymbolAddress((void**)&hv,    g_hv);
    cudaGetSymbolAddress((void**)&hw,    g_hw);
    cudaGetSymbolAddress((void**)&pq,    g_pq);
    cudaGetSymbolAddress((void**)&pk,    g_pk);
    cudaGetSymbolAddress((void**)&pv,    g_pv);
    cudaGetSymbolAddress((void**)&gattn, g_attn);

    cudaFuncSetAttribute(flash_tc,
                         cudaFuncAttributeMaxDynamicSharedMemorySize, F_SMEM);

    const int nBig = MM * DMODEL;          // 8,388,608
    const int nW   = DMODEL * DMODEL;      // 1,048,576

    f2h_inputs<<<dim3(nBig / 4 / 256, 1, 3), 256>>>(Q, K, V, hq, hk, hv, nBig);
    f2h_weights<<<dim3(nW / 4 / 256, 1, 4), 256>>>(W_q, W_k, W_v, W_o, hw, nW);

    // fused QKV projections (fp16 out; q pre-scaled by log2e/sqrt(Dk))
    gemm_qkv<<<dim3(DMODEL / 128, MM / 128, 3), 256>>>(
        hq, hk, hv, hw, b_q, b_k, b_v, pq, pk, pv);

    // tensor-core causal flash attention (BM=128, exp2 softmax)
    flash_tc<<<dim3(SS / 128, BB * HH), 256, F_SMEM>>>(pq, pk, pv, gattn);

    // O projection (fp32 out)
    gemm_hmma<<<dim3(DMODEL / 128, MM / 128), 256>>>(
        gattn, hw + 3 * (size_t)nW, b_o, out);
}

// round 16
// speedup vs baseline: 1.1752x; 1.0716x over previous
#include <cuda_runtime.h>
#include <cuda_fp16.h>
#include <math.h>
#include <stdint.h>

// Problem constants
#define BB 4
#define SS 2048
#define HH 16
#define DMODEL 1024
#define DK 64
#define MM (BB*SS)            // 8192

// ---------------- scratch (__device__ globals: allocation-guard safe) ------
__device__ __half g_hq[(size_t)MM*DMODEL];       // fp16 copies of raw inputs
__device__ __half g_hk[(size_t)MM*DMODEL];
__device__ __half g_hv[(size_t)MM*DMODEL];
__device__ __half g_hw[(size_t)4*DMODEL*DMODEL]; // Wq,Wk,Wv,Wo fp16
__device__ __half g_pq[(size_t)MM*DMODEL];       // projected q (scaled log2e/8)
__device__ __half g_pk[(size_t)MM*DMODEL];       // projected k
__device__ __half g_pv[(size_t)MM*DMODEL];       // projected v
__device__ __half g_attn[(size_t)MM*DMODEL];     // attention out [B,S,D] fp16

// ============================================================================
// PTX helpers — plain-ISA only (cp.async / ldmatrix / mma.sync). No tcgen05.
// ============================================================================
__device__ __forceinline__ uint32_t s2u(const void* p) {
    uint32_t a;
    asm("{ .reg .u64 t; cvta.to.shared.u64 t, %1; cvt.u32.u64 %0, t; }"
        : "=r"(a) : "l"(p));
    return a;
}
__device__ __forceinline__ void cp16(uint32_t dst, const void* src) {
    asm volatile("cp.async.cg.shared.global [%0], [%1], 16;" :: "r"(dst), "l"(src));
}
__device__ __forceinline__ void cp_commit() { asm volatile("cp.async.commit_group;"); }
__device__ __forceinline__ void cp_wait1()  { asm volatile("cp.async.wait_group 1;" ::: "memory"); }
__device__ __forceinline__ void cp_wait0()  { asm volatile("cp.async.wait_group 0;" ::: "memory"); }

__device__ __forceinline__ void ldsm4(uint32_t* r, uint32_t a) {
    asm volatile("ldmatrix.sync.aligned.m8n8.x4.shared.b16 {%0,%1,%2,%3}, [%4];"
                 : "=r"(r[0]), "=r"(r[1]), "=r"(r[2]), "=r"(r[3]) : "r"(a));
}
__device__ __forceinline__ void ldsm4t(uint32_t* r, uint32_t a) {
    asm volatile("ldmatrix.sync.aligned.m8n8.x4.trans.shared.b16 {%0,%1,%2,%3}, [%4];"
                 : "=r"(r[0]), "=r"(r[1]), "=r"(r[2]), "=r"(r[3]) : "r"(a));
}
__device__ __forceinline__ void mma16816(float* d, const uint32_t* a,
                                         uint32_t b0, uint32_t b1) {
    asm volatile(
        "mma.sync.aligned.m16n8k16.row.col.f32.f16.f16.f32 "
        "{%0,%1,%2,%3}, {%4,%5,%6,%7}, {%8,%9}, {%0,%1,%2,%3};"
        : "+f"(d[0]), "+f"(d[1]), "+f"(d[2]), "+f"(d[3])
        : "r"(a[0]), "r"(a[1]), "r"(a[2]), "r"(a[3]), "r"(b0), "r"(b1));
}
__device__ __forceinline__ uint32_t packh2(float x, float y) {
    __half2 h = __floats2half2_rn(x, y);
    return *reinterpret_cast<uint32_t*>(&h);
}

// ============================================================================
// fp32 -> fp16 conversions (2 launches)
// ============================================================================
__global__ __launch_bounds__(256)
void f2h_inputs(const float* __restrict__ s0, const float* __restrict__ s1,
                const float* __restrict__ s2,
                __half* __restrict__ d0, __half* __restrict__ d1,
                __half* __restrict__ d2, int n)
{
    const int z = blockIdx.z;
    const float* src = (z == 0) ? s0 : (z == 1) ? s1 : s2;
    __half*      dst = (z == 0) ? d0 : (z == 1) ? d1 : d2;
    int i = (blockIdx.x * blockDim.x + threadIdx.x) << 2;
    if (i >= n) return;
    float4 v = *(const float4*)(src + i);
    __half2* d = (__half2*)(dst + i);
    d[0] = __floats2half2_rn(v.x, v.y);
    d[1] = __floats2half2_rn(v.z, v.w);
}

__global__ __launch_bounds__(256)
void f2h_weights(const float* __restrict__ s0, const float* __restrict__ s1,
                 const float* __restrict__ s2, const float* __restrict__ s3,
                 __half* __restrict__ dst, int n)
{
    const int z = blockIdx.z;
    const float* src = (z == 0) ? s0 : (z == 1) ? s1 : (z == 2) ? s2 : s3;
    __half* d_ = dst + (size_t)z * n;
    int i = (blockIdx.x * blockDim.x + threadIdx.x) << 2;
    if (i >= n) return;
    float4 v = *(const float4*)(src + i);
    __half2* d = (__half2*)(d_ + i);
    d[0] = __floats2half2_rn(v.x, v.y);
    d[1] = __floats2half2_rn(v.z, v.w);
}

// ============================================================================
// HMMA GEMM core: CTA 128x128, K-step 64 (4 kk-substeps of 16), 256 thr =
// 8 warps (2Mx4N), warp tile 64x32. 2-stage cp.async double buffer in
// DYNAMIC smem, pitch 144B (flash-proven conflict-free). 16 k-steps ->
// 32 __syncthreads per CTA (half of K-step-32 version); 128 mma per sync-pair.
// grid = (1024/128, M/128[, z]).
// ============================================================================
#define GOPB  18432u            // bytes per operand per stage (128 rows x 144B)
#define GSTB  36864u            // bytes per stage (A+B)
#define G_SMEM 73728            // 2 stages

#define GEMM_ISSUE(Aptr, Wptr, st, k0)                                        \
    {   const uint32_t sob = (uint32_t)(st) * GSTB;                           \
        _Pragma("unroll") for (int it = 0; it < 4; ++it) {                    \
            const int idx = tid + it * 256;                                   \
            const int r = idx >> 3, c = idx & 7;                              \
            const uint32_t so = sob + (uint32_t)(r * 144 + c * 16);           \
            cp16(sbase + so,        (Aptr) + (size_t)(m0 + r) * DMODEL + (k0) + c * 8); \
            cp16(sbase + so + GOPB, (Wptr) + (size_t)(n0 + r) * DMODEL + (k0) + c * 8); } \
        cp_commit(); }

#define GEMM_BODY(Aptr, Wptr)                                                  \
    extern __shared__ __half gsm[];                                            \
    const uint32_t sbase = s2u(gsm);                                           \
    const int tid   = threadIdx.x;                                             \
    const int wid   = tid >> 5;                                                \
    const int lane  = tid & 31;                                                \
    const int warpM = wid >> 2;                                                \
    const int warpN = wid & 3;                                                 \
    const int m0 = blockIdx.y * 128;                                            \
    const int n0 = blockIdx.x * 128;                                            \
    float acc[4][4][4];                                                         \
    _Pragma("unroll") for (int i = 0; i < 4; i++)                               \
    _Pragma("unroll") for (int j = 0; j < 4; j++)                               \
    _Pragma("unroll") for (int k = 0; k < 4; k++) acc[i][j][k] = 0.f;           \
    GEMM_ISSUE(Aptr, Wptr, 0, 0)                                                \
    const int a_row_in = (lane & 15);                                           \
    const int a_k8     = (lane >> 4) << 4;                                      \
    const int b_nsub   = (lane & 7) + ((lane >> 4) & 1) * 8;                    \
    const int b_k8     = ((lane >> 3) & 1) << 4;                                \
    for (int s = 0; s < 16; ++s) {                                              \
        if (s + 1 < 16) { GEMM_ISSUE(Aptr, Wptr, (s + 1) & 1, (s + 1) * 64) cp_wait1(); } \
        else cp_wait0();                                                        \
        __syncthreads();                                                        \
        const uint32_t a_base = sbase + (uint32_t)(s & 1) * GSTB;               \
        const uint32_t b_base = a_base + GOPB;                                  \
        _Pragma("unroll") for (int kk = 0; kk < 4; ++kk) {                      \
            uint32_t ar[4][4];                                                  \
            _Pragma("unroll") for (int mf = 0; mf < 4; ++mf) {                  \
                const int row = warpM * 64 + mf * 16 + a_row_in;                \
                ldsm4(ar[mf], a_base + (uint32_t)(row * 144 + kk * 32 + a_k8)); } \
            uint32_t br[2][4];                                                  \
            _Pragma("unroll") for (int nf2 = 0; nf2 < 2; ++nf2) {               \
                const int nrow = warpN * 32 + nf2 * 16 + b_nsub;                \
                ldsm4(br[nf2], b_base + (uint32_t)(nrow * 144 + kk * 32 + b_k8)); } \
            _Pragma("unroll") for (int mf = 0; mf < 4; ++mf)                    \
            _Pragma("unroll") for (int nf = 0; nf < 4; ++nf)                    \
                mma16816(acc[mf][nf], ar[mf],                                   \
                         br[nf >> 1][(nf & 1) * 2],                             \
                         br[nf >> 1][(nf & 1) * 2 + 1]); }                      \
        __syncthreads(); }                                                      \
    const int rb = m0 + warpM * 64 + (lane >> 2);                               \
    const int cb = n0 + warpN * 32 + (lane & 3) * 2;

// ---- QKV projections (fused; fp16 out; q pre-scaled by log2e/sqrt(Dk)) -----
__global__ __launch_bounds__(256, 2)
void gemm_qkv(const __half* __restrict__ hq, const __half* __restrict__ hk,
              const __half* __restrict__ hv, const __half* __restrict__ hw,
              const float* __restrict__ bq, const float* __restrict__ bk,
              const float* __restrict__ bv,
              __half* __restrict__ pq, __half* __restrict__ pk,
              __half* __restrict__ pv)
{
    const int z = blockIdx.z;
    const __half* A    = (z == 0) ? hq : (z == 1) ? hk : hv;
    const __half* W    = hw + (size_t)z * DMODEL * DMODEL;
    const float*  bias = (z == 0) ? bq : (z == 1) ? bk : bv;
    __half*       C    = (z == 0) ? pq : (z == 1) ? pk : pv;
    const float scale  = (z == 0) ? 0.125f * 1.44269504f : 1.0f;  // log2e/8

    GEMM_BODY(A, W)

#pragma unroll
    for (int nf = 0; nf < 4; ++nf) {
        const int c = cb + nf * 8;
        const float b0 = __ldg(bias + c), b1 = __ldg(bias + c + 1);
#pragma unroll
        for (int mf = 0; mf < 4; ++mf) {
            const int r = rb + mf * 16;
            __half2 h0 = __floats2half2_rn((acc[mf][nf][0] + b0) * scale,
                                           (acc[mf][nf][1] + b1) * scale);
            __half2 h1 = __floats2half2_rn((acc[mf][nf][2] + b0) * scale,
                                           (acc[mf][nf][3] + b1) * scale);
            *(__half2*)(C + (size_t)r * DMODEL + c)       = h0;
            *(__half2*)(C + (size_t)(r + 8) * DMODEL + c) = h1;
        }
    }
}

// ---- O projection (fp32 out) -----------------------------------------------
__global__ __launch_bounds__(256, 2)
void gemm_hmma(const __half* __restrict__ Ain, const __half* __restrict__ Win,
               const float* __restrict__ bias, float* __restrict__ C)
{
    GEMM_BODY(Ain, Win)

#pragma unroll
    for (int nf = 0; nf < 4; ++nf) {
        const int c = cb + nf * 8;
        const float b0 = __ldg(bias + c), b1 = __ldg(bias + c + 1);
#pragma unroll
        for (int mf = 0; mf < 4; ++mf) {
            const int r = rb + mf * 16;
            *(float2*)(C + (size_t)r * DMODEL + c) =
                make_float2(acc[mf][nf][0] + b0, acc[mf][nf][1] + b1);
            *(float2*)(C + (size_t)(r + 8) * DMODEL + c) =
                make_float2(acc[mf][nf][2] + b0, acc[mf][nf][3] + b1);
        }
    }
}

// ============================================================================
// Tensor-core flash attention (R14/R15 config — unchanged, 156-161us).
// BM=128 (8 warps, 256 thr), BN=64, exp2-domain softmax. Q frags in regs;
// P register-reuse; V via ldmatrix.trans; double-buffered cp.async K/V;
// ONE __syncthreads per KV tile. grid=(16, B*H), heavy tiles first.
// ============================================================================
#define FP 72           // pitch in halves
#define FPB 144         // pitch in bytes
#define F_QB   18432    // Q bytes (128 rows)
#define F_KVB  9216     // one operand tile bytes (64 rows)
#define F_SMEM (F_QB + 4*F_KVB)   // 55296

__global__ __launch_bounds__(256)
void flash_tc(const __half* __restrict__ pq, const __half* __restrict__ pk,
              const __half* __restrict__ pv, __half* __restrict__ gout)
{
    extern __shared__ __half fsm[];
    const uint32_t uQ = s2u(fsm);

    const int tid  = threadIdx.x;
    const int lane = tid & 31;
    const int wid  = tid >> 5;
    const int bx   = (int)gridDim.x - 1 - (int)blockIdx.x;  // heavy first
    const int bh   = blockIdx.y;
    const int b_   = bh >> 4;
    const int h    = bh & (HH - 1);
    const int q0   = bx * 128;
    const int nt   = 2 * bx + 2;           // KV tiles
    const size_t rowbase = (size_t)b_ * SS;
    const int coloff = h * DK;

    // Q tile load (128 rows; group 0)
    {
        const __half* qg = pq + (rowbase + q0) * DMODEL + coloff;
#pragma unroll
        for (int it = 0; it < 4; ++it) {
            const int idx = tid + it * 256;
            const int r = idx >> 3, c = idx & 7;
            cp16(uQ + (uint32_t)(r * FPB + c * 16), qg + (size_t)r * DMODEL + c * 8);
        }
        cp_commit();
    }

#define LOAD_KV(kt_, buf_)                                                     \
    {   const __half* kg = pk + (rowbase + (kt_) * 64) * DMODEL + coloff;      \
        const __half* vg = pv + (rowbase + (kt_) * 64) * DMODEL + coloff;      \
        const uint32_t kb = uQ + F_QB + (uint32_t)(buf_) * (2 * F_KVB);        \
        _Pragma("unroll") for (int it = 0; it < 2; ++it) {                     \
            const int idx = tid + it * 256;                                    \
            const int r = idx >> 3, c = idx & 7;                               \
            const uint32_t so = (uint32_t)(r * FPB + c * 16);                  \
            cp16(kb + so,         kg + (size_t)r * DMODEL + c * 8);            \
            cp16(kb + F_KVB + so, vg + (size_t)r * DMODEL + c * 8); }          \
        cp_commit(); }

    LOAD_KV(0, 0)
    cp_wait1();          // Q done (KV0 may be in flight)
    __syncthreads();

    // Q fragments -> registers (once)
    const int arow = lane & 15;
    const int ak8  = (lane >> 4) << 4;   // bytes
    uint32_t qf[4][4];
#pragma unroll
    for (int j = 0; j < 4; ++j)
        ldsm4(qf[j], uQ + (uint32_t)((wid * 16 + arow) * FPB + j * 32 + ak8));

    float oacc[8][4];
#pragma unroll
    for (int nf = 0; nf < 8; ++nf)
#pragma unroll
        for (int k = 0; k < 4; ++k) oacc[nf][k] = 0.f;
    float m0 = -1e30f, m1 = -1e30f, l0 = 0.f, l1 = 0.f;

    const int lr0 = wid * 16 + (lane >> 2);   // local query row of regs 0,1
    const int lr1 = lr0 + 8;                  // regs 2,3

    for (int kt = 0; kt < nt; ++kt) {
        cp_wait0();                 // KV kt landed
        __syncthreads();            // publish; frees old buffer
        if (kt + 1 < nt) LOAD_KV(kt + 1, (kt + 1) & 1)

        const uint32_t ukb = uQ + F_QB + (uint32_t)(kt & 1) * (2 * F_KVB);
        const uint32_t uvb = ukb + F_KVB;

        // ---- S = Q K^T (log2 domain) ----
        float s[8][4];
#pragma unroll
        for (int nf = 0; nf < 8; ++nf)
#pragma unroll
            for (int k = 0; k < 4; ++k) s[nf][k] = 0.f;

#pragma unroll
        for (int j = 0; j < 4; ++j) {
#pragma unroll
            for (int nb = 0; nb < 4; ++nb) {
                uint32_t br[4];
                ldsm4(br, ukb + (uint32_t)((nb * 16 + arow) * FPB + j * 32 + ak8));
                mma16816(s[2 * nb],     qf[j], br[0], br[2]);
                mma16816(s[2 * nb + 1], qf[j], br[1], br[3]);
            }
        }

        // ---- causal mask (two partial tiles per CTA) ----
        if (kt >= 2 * bx) {
            const int off = q0 - kt * 64;   // 0 or -64
#pragma unroll
            for (int nf = 0; nf < 8; ++nf) {
                const int kc0 = nf * 8 + (lane & 3) * 2;
                const int kc1 = kc0 + 1;
                if (kc0 > lr0 + off) s[nf][0] = -1e30f;
                if (kc1 > lr0 + off) s[nf][1] = -1e30f;
                if (kc0 > lr1 + off) s[nf][2] = -1e30f;
                if (kc1 > lr1 + off) s[nf][3] = -1e30f;
            }
        }

        // ---- online softmax (exp2, fragment layout) ----
        float mx0 = -1e30f, mx1 = -1e30f;
#pragma unroll
        for (int nf = 0; nf < 8; ++nf) {
            mx0 = fmaxf(mx0, fmaxf(s[nf][0], s[nf][1]));
            mx1 = fmaxf(mx1, fmaxf(s[nf][2], s[nf][3]));
        }
        mx0 = fmaxf(mx0, __shfl_xor_sync(0xffffffffu, mx0, 1));
        mx0 = fmaxf(mx0, __shfl_xor_sync(0xffffffffu, mx0, 2));
        mx1 = fmaxf(mx1, __shfl_xor_sync(0xffffffffu, mx1, 1));
        mx1 = fmaxf(mx1, __shfl_xor_sync(0xffffffffu, mx1, 2));

        const float mn0 = fmaxf(m0, mx0);
        const float mn1 = fmaxf(m1, mx1);
        const float a0 = exp2f(m0 - mn0);
        const float a1 = exp2f(m1 - mn1);
        float sum0 = 0.f, sum1 = 0.f;
#pragma unroll
        for (int nf = 0; nf < 8; ++nf) {
            s[nf][0] = exp2f(s[nf][0] - mn0);
            s[nf][1] = exp2f(s[nf][1] - mn0);
            s[nf][2] = exp2f(s[nf][2] - mn1);
            s[nf][3] = exp2f(s[nf][3] - mn1);
            sum0 += s[nf][0] + s[nf][1];
            sum1 += s[nf][2] + s[nf][3];
        }
        sum0 += __shfl_xor_sync(0xffffffffu, sum0, 1);
        sum0 += __shfl_xor_sync(0xffffffffu, sum0, 2);
        sum1 += __shfl_xor_sync(0xffffffffu, sum1, 1);
        sum1 += __shfl_xor_sync(0xffffffffu, sum1, 2);
        l0 = l0 * a0 + sum0;  m0 = mn0;
        l1 = l1 * a1 + sum1;  m1 = mn1;
#pragma unroll
        for (int nf = 0; nf < 8; ++nf) {
            oacc[nf][0] *= a0; oacc[nf][1] *= a0;
            oacc[nf][2] *= a1; oacc[nf][3] *= a1;
        }

        // ---- P (fp16 A-frags, register reuse) ----
        uint32_t pa[4][4];
#pragma unroll
        for (int j = 0; j < 4; ++j) {
            pa[j][0] = packh2(s[2 * j][0],     s[2 * j][1]);
            pa[j][1] = packh2(s[2 * j][2],     s[2 * j][3]);
            pa[j][2] = packh2(s[2 * j + 1][0], s[2 * j + 1][1]);
            pa[j][3] = packh2(s[2 * j + 1][2], s[2 * j + 1][3]);
        }

        // ---- O += P V  (V via ldmatrix.trans) ----
#pragma unroll
        for (int j = 0; j < 4; ++j) {
#pragma unroll
            for (int db = 0; db < 4; ++db) {
                uint32_t bv[4];
                ldsm4t(bv, uvb + (uint32_t)((j * 16 + arow) * FPB
                                            + (db * 16 + (lane >> 4) * 8) * 2));
                mma16816(oacc[2 * db],     pa[j], bv[0], bv[1]);
                mma16816(oacc[2 * db + 1], pa[j], bv[2], bv[3]);
            }
        }
    }

    // ---- epilogue: normalize, write fp16 [B,S,D] ----
    const float inv0 = 1.0f / l0;
    const float inv1 = 1.0f / l1;
    const size_t gr0 = rowbase + q0 + (size_t)lr0;
    const size_t gr1 = gr0 + 8;
#pragma unroll
    for (int nf = 0; nf < 8; ++nf) {
        const int col = coloff + nf * 8 + (lane & 3) * 2;
        *(__half2*)(gout + gr0 * DMODEL + col) =
            __floats2half2_rn(oacc[nf][0] * inv0, oacc[nf][1] * inv0);
        *(__half2*)(gout + gr1 * DMODEL + col) =
            __floats2half2_rn(oacc[nf][2] * inv1, oacc[nf][3] * inv1);
    }
#undef LOAD_KV
}

// ============================================================================
// launch
// ============================================================================
extern "C" void kernel_launch(void* const* d_in, const int* in_sizes, int n_in,
                              void* d_out, int out_size)
{
    const float* Q   = (const float*)d_in[0];
    const float* K   = (const float*)d_in[1];
    const float* V   = (const float*)d_in[2];
    // d_in[3] = mask (causal tril; handled analytically)
    const float* W_q = (const float*)d_in[4];
    const float* b_q = (const float*)d_in[5];
    const float* W_k = (const float*)d_in[6];
    const float* b_k = (const float*)d_in[7];
    const float* W_v = (const float*)d_in[8];
    const float* b_v = (const float*)d_in[9];
    const float* W_o = (const float*)d_in[10];
    const float* b_o = (const float*)d_in[11];
    float* out = (float*)d_out;

    __half *hq, *hk, *hv, *hw, *pq, *pk, *pv, *gattn;
    cudaGetSymbolAddress((void**)&hq,    g_hq);
    cudaGetSymbolAddress((void**)&hk,    g_hk);
    cudaGetSymbolAddress((void**)&hv,    g_hv);
    cudaGetSymbolAddress((void**)&hw,    g_hw);
    cudaGetSymbolAddress((void**)&pq,    g_pq);
    cudaGetSymbolAddress((void**)&pk,    g_pk);
    cudaGetSymbolAddress((void**)&pv,    g_pv);
    cudaGetSymbolAddress((void**)&gattn, g_attn);

    cudaFuncSetAttribute(gemm_qkv,
                         cudaFuncAttributeMaxDynamicSharedMemorySize, G_SMEM);
    cudaFuncSetAttribute(gemm_hmma,
                         cudaFuncAttributeMaxDynamicSharedMemorySize, G_SMEM);
    cudaFuncSetAttribute(flash_tc,
                         cudaFuncAttributeMaxDynamicSharedMemorySize, F_SMEM);

    const int nBig = MM * DMODEL;          // 8,388,608
    const int nW   = DMODEL * DMODEL;      // 1,048,576

    f2h_inputs<<<dim3(nBig / 4 / 256, 1, 3), 256>>>(Q, K, V, hq, hk, hv, nBig);
    f2h_weights<<<dim3(nW / 4 / 256, 1, 4), 256>>>(W_q, W_k, W_v, W_o, hw, nW);

    // fused QKV projections (fp16 out; q pre-scaled by log2e/sqrt(Dk))
    gemm_qkv<<<dim3(DMODEL / 128, MM / 128, 3), 256, G_SMEM>>>(
        hq, hk, hv, hw, b_q, b_k, b_v, pq, pk, pv);

    // tensor-core causal flash attention (BM=128, exp2 softmax)
    flash_tc<<<dim3(SS / 128, BB * HH), 256, F_SMEM>>>(pq, pk, pv, gattn);

    // O projection (fp32 out)
    gemm_hmma<<<dim3(DMODEL / 128, MM / 128), 256, G_SMEM>>>(
        gattn, hw + 3 * (size_t)nW, b_o, out);
}

// round 17
// speedup vs baseline: 1.1989x; 1.0202x over previous
#include <cuda_runtime.h>
#include <cuda_fp16.h>
#include <math.h>
#include <stdint.h>

// Problem constants
#define BB 4
#define SS 2048
#define HH 16
#define DMODEL 1024
#define DK 64
#define MM (BB*SS)            // 8192

// ---------------- scratch (__device__ globals: allocation-guard safe) ------
__device__ __half g_hq[(size_t)MM*DMODEL];       // fp16 copies of raw inputs
__device__ __half g_hk[(size_t)MM*DMODEL];
__device__ __half g_hv[(size_t)MM*DMODEL];
__device__ __half g_hw[(size_t)4*DMODEL*DMODEL]; // Wq,Wk,Wv,Wo fp16
__device__ __half g_pq[(size_t)MM*DMODEL];       // projected q (scaled log2e/8)
__device__ __half g_pk[(size_t)MM*DMODEL];       // projected k
__device__ __half g_pv[(size_t)MM*DMODEL];       // projected v
__device__ __half g_attn[(size_t)MM*DMODEL];     // attention out [B,S,D] fp16

// ============================================================================
// PTX helpers — plain-ISA only (cp.async / ldmatrix / mma.sync). No tcgen05.
// ============================================================================
__device__ __forceinline__ uint32_t s2u(const void* p) {
    uint32_t a;
    asm("{ .reg .u64 t; cvta.to.shared.u64 t, %1; cvt.u32.u64 %0, t; }"
        : "=r"(a) : "l"(p));
    return a;
}
__device__ __forceinline__ void cp16(uint32_t dst, const void* src) {
    asm volatile("cp.async.cg.shared.global [%0], [%1], 16;" :: "r"(dst), "l"(src));
}
__device__ __forceinline__ void cp_commit() { asm volatile("cp.async.commit_group;"); }
__device__ __forceinline__ void cp_wait1()  { asm volatile("cp.async.wait_group 1;" ::: "memory"); }
__device__ __forceinline__ void cp_wait0()  { asm volatile("cp.async.wait_group 0;" ::: "memory"); }

__device__ __forceinline__ void ldsm4(uint32_t* r, uint32_t a) {
    asm volatile("ldmatrix.sync.aligned.m8n8.x4.shared.b16 {%0,%1,%2,%3}, [%4];"
                 : "=r"(r[0]), "=r"(r[1]), "=r"(r[2]), "=r"(r[3]) : "r"(a));
}
__device__ __forceinline__ void ldsm4t(uint32_t* r, uint32_t a) {
    asm volatile("ldmatrix.sync.aligned.m8n8.x4.trans.shared.b16 {%0,%1,%2,%3}, [%4];"
                 : "=r"(r[0]), "=r"(r[1]), "=r"(r[2]), "=r"(r[3]) : "r"(a));
}
__device__ __forceinline__ void mma16816(float* d, const uint32_t* a,
                                         uint32_t b0, uint32_t b1) {
    asm volatile(
        "mma.sync.aligned.m16n8k16.row.col.f32.f16.f16.f32 "
        "{%0,%1,%2,%3}, {%4,%5,%6,%7}, {%8,%9}, {%0,%1,%2,%3};"
        : "+f"(d[0]), "+f"(d[1]), "+f"(d[2]), "+f"(d[3])
        : "r"(a[0]), "r"(a[1]), "r"(a[2]), "r"(a[3]), "r"(b0), "r"(b1));
}
__device__ __forceinline__ uint32_t packh2(float x, float y) {
    __half2 h = __floats2half2_rn(x, y);
    return *reinterpret_cast<uint32_t*>(&h);
}

// ============================================================================
// fp32 -> fp16 conversions (2 launches)
// ============================================================================
__global__ __launch_bounds__(256)
void f2h_inputs(const float* __restrict__ s0, const float* __restrict__ s1,
                const float* __restrict__ s2,
                __half* __restrict__ d0, __half* __restrict__ d1,
                __half* __restrict__ d2, int n)
{
    const int z = blockIdx.z;
    const float* src = (z == 0) ? s0 : (z == 1) ? s1 : s2;
    __half*      dst = (z == 0) ? d0 : (z == 1) ? d1 : d2;
    int i = (blockIdx.x * blockDim.x + threadIdx.x) << 2;
    if (i >= n) return;
    float4 v = *(const float4*)(src + i);
    __half2* d = (__half2*)(dst + i);
    d[0] = __floats2half2_rn(v.x, v.y);
    d[1] = __floats2half2_rn(v.z, v.w);
}

__global__ __launch_bounds__(256)
void f2h_weights(const float* __restrict__ s0, const float* __restrict__ s1,
                 const float* __restrict__ s2, const float* __restrict__ s3,
                 __half* __restrict__ dst, int n)
{
    const int z = blockIdx.z;
    const float* src = (z == 0) ? s0 : (z == 1) ? s1 : (z == 2) ? s2 : s3;
    __half* d_ = dst + (size_t)z * n;
    int i = (blockIdx.x * blockDim.x + threadIdx.x) << 2;
    if (i >= n) return;
    float4 v = *(const float4*)(src + i);
    __half2* d = (__half2*)(d_ + i);
    d[0] = __floats2half2_rn(v.x, v.y);
    d[1] = __floats2half2_rn(v.z, v.w);
}

// ============================================================================
// HMMA GEMM core: CTA 128x128, K-step 64 (4 kk-substeps of 16), 256 thr =
// 8 warps (2Mx4N), warp tile 64x32. 2-stage cp.async double buffer, dynamic
// smem, pitch 144B. Flash-style ordering: ONE __syncthreads per k-step
// (wait0 -> sync -> issue next -> compute). 16 k-steps -> 17 syncs per CTA.
// grid = (1024/128, M/128[, z]).
// ============================================================================
#define GOPB  18432u            // bytes per operand per stage (128 rows x 144B)
#define GSTB  36864u            // bytes per stage (A+B)
#define G_SMEM 73728            // 2 stages

#define GEMM_ISSUE(Aptr, Wptr, st, k0)                                        \
    {   const uint32_t sob = (uint32_t)(st) * GSTB;                           \
        _Pragma("unroll") for (int it = 0; it < 4; ++it) {                    \
            const int idx = tid + it * 256;                                   \
            const int r = idx >> 3, c = idx & 7;                              \
            const uint32_t so = sob + (uint32_t)(r * 144 + c * 16);           \
            cp16(sbase + so,        (Aptr) + (size_t)(m0 + r) * DMODEL + (k0) + c * 8); \
            cp16(sbase + so + GOPB, (Wptr) + (size_t)(n0 + r) * DMODEL + (k0) + c * 8); } \
        cp_commit(); }

#define GEMM_BODY(Aptr, Wptr)                                                  \
    extern __shared__ __half gsm[];                                            \
    const uint32_t sbase = s2u(gsm);                                           \
    const int tid   = threadIdx.x;                                             \
    const int wid   = tid >> 5;                                                \
    const int lane  = tid & 31;                                                \
    const int warpM = wid >> 2;                                                \
    const int warpN = wid & 3;                                                 \
    const int m0 = blockIdx.y * 128;                                            \
    const int n0 = blockIdx.x * 128;                                            \
    float acc[4][4][4];                                                         \
    _Pragma("unroll") for (int i = 0; i < 4; i++)                               \
    _Pragma("unroll") for (int j = 0; j < 4; j++)                               \
    _Pragma("unroll") for (int k = 0; k < 4; k++) acc[i][j][k] = 0.f;           \
    GEMM_ISSUE(Aptr, Wptr, 0, 0)                                                \
    const int a_row_in = (lane & 15);                                           \
    const int a_k8     = (lane >> 4) << 4;                                      \
    const int b_nsub   = (lane & 7) + ((lane >> 4) & 1) * 8;                    \
    const int b_k8     = ((lane >> 3) & 1) << 4;                                \
    for (int s = 0; s < 16; ++s) {                                              \
        cp_wait0();                 /* load s landed (only one outstanding) */  \
        __syncthreads();            /* publish s; certifies buf (s+1)&1 free */ \
        if (s + 1 < 16) GEMM_ISSUE(Aptr, Wptr, (s + 1) & 1, (s + 1) * 64)       \
        const uint32_t a_base = sbase + (uint32_t)(s & 1) * GSTB;               \
        const uint32_t b_base = a_base + GOPB;                                  \
        _Pragma("unroll") for (int kk = 0; kk < 4; ++kk) {                      \
            uint32_t ar[4][4];                                                  \
            _Pragma("unroll") for (int mf = 0; mf < 4; ++mf) {                  \
                const int row = warpM * 64 + mf * 16 + a_row_in;                \
                ldsm4(ar[mf], a_base + (uint32_t)(row * 144 + kk * 32 + a_k8)); } \
            uint32_t br[2][4];                                                  \
            _Pragma("unroll") for (int nf2 = 0; nf2 < 2; ++nf2) {               \
                const int nrow = warpN * 32 + nf2 * 16 + b_nsub;                \
                ldsm4(br[nf2], b_base + (uint32_t)(nrow * 144 + kk * 32 + b_k8)); } \
            _Pragma("unroll") for (int mf = 0; mf < 4; ++mf)                    \
            _Pragma("unroll") for (int nf = 0; nf < 4; ++nf)                    \
                mma16816(acc[mf][nf], ar[mf],                                   \
                         br[nf >> 1][(nf & 1) * 2],                             \
                         br[nf >> 1][(nf & 1) * 2 + 1]); }                      \
    }                                                                           \
    const int rb = m0 + warpM * 64 + (lane >> 2);                               \
    const int cb = n0 + warpN * 32 + (lane & 3) * 2;

// ---- QKV projections (fused; fp16 out; q pre-scaled by log2e/sqrt(Dk)) -----
__global__ __launch_bounds__(256, 2)
void gemm_qkv(const __half* __restrict__ hq, const __half* __restrict__ hk,
              const __half* __restrict__ hv, const __half* __restrict__ hw,
              const float* __restrict__ bq, const float* __restrict__ bk,
              const float* __restrict__ bv,
              __half* __restrict__ pq, __half* __restrict__ pk,
              __half* __restrict__ pv)
{
    const int z = blockIdx.z;
    const __half* A    = (z == 0) ? hq : (z == 1) ? hk : hv;
    const __half* W    = hw + (size_t)z * DMODEL * DMODEL;
    const float*  bias = (z == 0) ? bq : (z == 1) ? bk : bv;
    __half*       C    = (z == 0) ? pq : (z == 1) ? pk : pv;
    const float scale  = (z == 0) ? 0.125f * 1.44269504f : 1.0f;  // log2e/8

    GEMM_BODY(A, W)

#pragma unroll
    for (int nf = 0; nf < 4; ++nf) {
        const int c = cb + nf * 8;
        const float b0 = __ldg(bias + c), b1 = __ldg(bias + c + 1);
#pragma unroll
        for (int mf = 0; mf < 4; ++mf) {
            const int r = rb + mf * 16;
            __half2 h0 = __floats2half2_rn((acc[mf][nf][0] + b0) * scale,
                                           (acc[mf][nf][1] + b1) * scale);
            __half2 h1 = __floats2half2_rn((acc[mf][nf][2] + b0) * scale,
                                           (acc[mf][nf][3] + b1) * scale);
            *(__half2*)(C + (size_t)r * DMODEL + c)       = h0;
            *(__half2*)(C + (size_t)(r + 8) * DMODEL + c) = h1;
        }
    }
}

// ---- O projection (fp32 out) -----------------------------------------------
__global__ __launch_bounds__(256, 2)
void gemm_hmma(const __half* __restrict__ Ain, const __half* __restrict__ Win,
               const float* __restrict__ bias, float* __restrict__ C)
{
    GEMM_BODY(Ain, Win)

#pragma unroll
    for (int nf = 0; nf < 4; ++nf) {
        const int c = cb + nf * 8;
        const float b0 = __ldg(bias + c), b1 = __ldg(bias + c + 1);
#pragma unroll
        for (int mf = 0; mf < 4; ++mf) {
            const int r = rb + mf * 16;
            *(float2*)(C + (size_t)r * DMODEL + c) =
                make_float2(acc[mf][nf][0] + b0, acc[mf][nf][1] + b1);
            *(float2*)(C + (size_t)(r + 8) * DMODEL + c) =
                make_float2(acc[mf][nf][2] + b0, acc[mf][nf][3] + b1);
        }
    }
}

// ============================================================================
// Tensor-core flash attention (unchanged from R16 — 152us measured).
// BM=128 (8 warps, 256 thr), BN=64, exp2-domain softmax. Q frags in regs;
// P register-reuse; V via ldmatrix.trans; double-buffered cp.async K/V;
// ONE __syncthreads per KV tile. grid=(16, B*H), heavy tiles first.
// ============================================================================
#define FP 72           // pitch in halves
#define FPB 144         // pitch in bytes
#define F_QB   18432    // Q bytes (128 rows)
#define F_KVB  9216     // one operand tile bytes (64 rows)
#define F_SMEM (F_QB + 4*F_KVB)   // 55296

__global__ __launch_bounds__(256)
void flash_tc(const __half* __restrict__ pq, const __half* __restrict__ pk,
              const __half* __restrict__ pv, __half* __restrict__ gout)
{
    extern __shared__ __half fsm[];
    const uint32_t uQ = s2u(fsm);

    const int tid  = threadIdx.x;
    const int lane = tid & 31;
    const int wid  = tid >> 5;
    const int bx   = (int)gridDim.x - 1 - (int)blockIdx.x;  // heavy first
    const int bh   = blockIdx.y;
    const int b_   = bh >> 4;
    const int h    = bh & (HH - 1);
    const int q0   = bx * 128;
    const int nt   = 2 * bx + 2;           // KV tiles
    const size_t rowbase = (size_t)b_ * SS;
    const int coloff = h * DK;

    // Q tile load (128 rows; group 0)
    {
        const __half* qg = pq + (rowbase + q0) * DMODEL + coloff;
#pragma unroll
        for (int it = 0; it < 4; ++it) {
            const int idx = tid + it * 256;
            const int r = idx >> 3, c = idx & 7;
            cp16(uQ + (uint32_t)(r * FPB + c * 16), qg + (size_t)r * DMODEL + c * 8);
        }
        cp_commit();
    }

#define LOAD_KV(kt_, buf_)                                                     \
    {   const __half* kg = pk + (rowbase + (kt_) * 64) * DMODEL + coloff;      \
        const __half* vg = pv + (rowbase + (kt_) * 64) * DMODEL + coloff;      \
        const uint32_t kb = uQ + F_QB + (uint32_t)(buf_) * (2 * F_KVB);        \
        _Pragma("unroll") for (int it = 0; it < 2; ++it) {                     \
            const int idx = tid + it * 256;                                    \
            const int r = idx >> 3, c = idx & 7;                               \
            const uint32_t so = (uint32_t)(r * FPB + c * 16);                  \
            cp16(kb + so,         kg + (size_t)r * DMODEL + c * 8);            \
            cp16(kb + F_KVB + so, vg + (size_t)r * DMODEL + c * 8); }          \
        cp_commit(); }

    LOAD_KV(0, 0)
    cp_wait1();          // Q done (KV0 may be in flight)
    __syncthreads();

    // Q fragments -> registers (once)
    const int arow = lane & 15;
    const int ak8  = (lane >> 4) << 4;   // bytes
    uint32_t qf[4][4];
#pragma unroll
    for (int j = 0; j < 4; ++j)
        ldsm4(qf[j], uQ + (uint32_t)((wid * 16 + arow) * FPB + j * 32 + ak8));

    float oacc[8][4];
#pragma unroll
    for (int nf = 0; nf < 8; ++nf)
#pragma unroll
        for (int k = 0; k < 4; ++k) oacc[nf][k] = 0.f;
    float m0 = -1e30f, m1 = -1e30f, l0 = 0.f, l1 = 0.f;

    const int lr0 = wid * 16 + (lane >> 2);   // local query row of regs 0,1
    const int lr1 = lr0 + 8;                  // regs 2,3

    for (int kt = 0; kt < nt; ++kt) {
        cp_wait0();                 // KV kt landed
        __syncthreads();            // publish; frees old buffer
        if (kt + 1 < nt) LOAD_KV(kt + 1, (kt + 1) & 1)

        const uint32_t ukb = uQ + F_QB + (uint32_t)(kt & 1) * (2 * F_KVB);
        const uint32_t uvb = ukb + F_KVB;

        // ---- S = Q K^T (log2 domain) ----
        float s[8][4];
#pragma unroll
        for (int nf = 0; nf < 8; ++nf)
#pragma unroll
            for (int k = 0; k < 4; ++k) s[nf][k] = 0.f;

#pragma unroll
        for (int j = 0; j < 4; ++j) {
#pragma unroll
            for (int nb = 0; nb < 4; ++nb) {
                uint32_t br[4];
                ldsm4(br, ukb + (uint32_t)((nb * 16 + arow) * FPB + j * 32 + ak8));
                mma16816(s[2 * nb],     qf[j], br[0], br[2]);
                mma16816(s[2 * nb + 1], qf[j], br[1], br[3]);
            }
        }

        // ---- causal mask (two partial tiles per CTA) ----
        if (kt >= 2 * bx) {
            const int off = q0 - kt * 64;   // 0 or -64
#pragma unroll
            for (int nf = 0; nf < 8; ++nf) {
                const int kc0 = nf * 8 + (lane & 3) * 2;
                const int kc1 = kc0 + 1;
                if (kc0 > lr0 + off) s[nf][0] = -1e30f;
                if (kc1 > lr0 + off) s[nf][1] = -1e30f;
                if (kc0 > lr1 + off) s[nf][2] = -1e30f;
                if (kc1 > lr1 + off) s[nf][3] = -1e30f;
            }
        }

        // ---- online softmax (exp2, fragment layout) ----
        float mx0 = -1e30f, mx1 = -1e30f;
#pragma unroll
        for (int nf = 0; nf < 8; ++nf) {
            mx0 = fmaxf(mx0, fmaxf(s[nf][0], s[nf][1]));
            mx1 = fmaxf(mx1, fmaxf(s[nf][2], s[nf][3]));
        }
        mx0 = fmaxf(mx0, __shfl_xor_sync(0xffffffffu, mx0, 1));
        mx0 = fmaxf(mx0, __shfl_xor_sync(0xffffffffu, mx0, 2));
        mx1 = fmaxf(mx1, __shfl_xor_sync(0xffffffffu, mx1, 1));
        mx1 = fmaxf(mx1, __shfl_xor_sync(0xffffffffu, mx1, 2));

        const float mn0 = fmaxf(m0, mx0);
        const float mn1 = fmaxf(m1, mx1);
        const float a0 = exp2f(m0 - mn0);
        const float a1 = exp2f(m1 - mn1);
        float sum0 = 0.f, sum1 = 0.f;
#pragma unroll
        for (int nf = 0; nf < 8; ++nf) {
            s[nf][0] = exp2f(s[nf][0] - mn0);
            s[nf][1] = exp2f(s[nf][1] - mn0);
            s[nf][2] = exp2f(s[nf][2] - mn1);
            s[nf][3] = exp2f(s[nf][3] - mn1);
            sum0 += s[nf][0] + s[nf][1];
            sum1 += s[nf][2] + s[nf][3];
        }
        sum0 += __shfl_xor_sync(0xffffffffu, sum0, 1);
        sum0 += __shfl_xor_sync(0xffffffffu, sum0, 2);
        sum1 += __shfl_xor_sync(0xffffffffu, sum1, 1);
        sum1 += __shfl_xor_sync(0xffffffffu, sum1, 2);
        l0 = l0 * a0 + sum0;  m0 = mn0;
        l1 = l1 * a1 + sum1;  m1 = mn1;
#pragma unroll
        for (int nf = 0; nf < 8; ++nf) {
            oacc[nf][0] *= a0; oacc[nf][1] *= a0;
            oacc[nf][2] *= a1; oacc[nf][3] *= a1;
        }

        // ---- P (fp16 A-frags, register reuse) ----
        uint32_t pa[4][4];
#pragma unroll
        for (int j = 0; j < 4; ++j) {
            pa[j][0] = packh2(s[2 * j][0],     s[2 * j][1]);
            pa[j][1] = packh2(s[2 * j][2],     s[2 * j][3]);
            pa[j][2] = packh2(s[2 * j + 1][0], s[2 * j + 1][1]);
            pa[j][3] = packh2(s[2 * j + 1][2], s[2 * j + 1][3]);
        }

        // ---- O += P V  (V via ldmatrix.trans) ----
#pragma unroll
        for (int j = 0; j < 4; ++j) {
#pragma unroll
            for (int db = 0; db < 4; ++db) {
                uint32_t bv[4];
                ldsm4t(bv, uvb + (uint32_t)((j * 16 + arow) * FPB
                                            + (db * 16 + (lane >> 4) * 8) * 2));
                mma16816(oacc[2 * db],     pa[j], bv[0], bv[1]);
                mma16816(oacc[2 * db + 1], pa[j], bv[2], bv[3]);
            }
        }
    }

    // ---- epilogue: normalize, write fp16 [B,S,D] ----
    const float inv0 = 1.0f / l0;
    const float inv1 = 1.0f / l1;
    const size_t gr0 = rowbase + q0 + (size_t)lr0;
    const size_t gr1 = gr0 + 8;
#pragma unroll
    for (int nf = 0; nf < 8; ++nf) {
        const int col = coloff + nf * 8 + (lane & 3) * 2;
        *(__half2*)(gout + gr0 * DMODEL + col) =
            __floats2half2_rn(oacc[nf][0] * inv0, oacc[nf][1] * inv0);
        *(__half2*)(gout + gr1 * DMODEL + col) =
            __floats2half2_rn(oacc[nf][2] * inv1, oacc[nf][3] * inv1);
    }
#undef LOAD_KV
}

// ============================================================================
// launch
// ============================================================================
extern "C" void kernel_launch(void* const* d_in, const int* in_sizes, int n_in,
                              void* d_out, int out_size)
{
    const float* Q   = (const float*)d_in[0];
    const float* K   = (const float*)d_in[1];
    const float* V   = (const float*)d_in[2];
    // d_in[3] = mask (causal tril; handled analytically)
    const float* W_q = (const float*)d_in[4];
    const float* b_q = (const float*)d_in[5];
    const float* W_k = (const float*)d_in[6];
    const float* b_k = (const float*)d_in[7];
    const float* W_v = (const float*)d_in[8];
    const float* b_v = (const float*)d_in[9];
    const float* W_o = (const float*)d_in[10];
    const float* b_o = (const float*)d_in[11];
    float* out = (float*)d_out;

    __half *hq, *hk, *hv, *hw, *pq, *pk, *pv, *gattn;
    cudaGetSymbolAddress((void**)&hq,    g_hq);
    cudaGetSymbolAddress((void**)&hk,    g_hk);
    cudaGetSymbolAddress((void**)&hv,    g_hv);
    cudaGetSymbolAddress((void**)&hw,    g_hw);
    cudaGetSymbolAddress((void**)&pq,    g_pq);
    cudaGetSymbolAddress((void**)&pk,    g_pk);
    cudaGetSymbolAddress((void**)&pv,    g_pv);
    cudaGetSymbolAddress((void**)&gattn, g_attn);

    cudaFuncSetAttribute(gemm_qkv,
                         cudaFuncAttributeMaxDynamicSharedMemorySize, G_SMEM);
    cudaFuncSetAttribute(gemm_hmma,
                         cudaFuncAttributeMaxDynamicSharedMemorySize, G_SMEM);
    cudaFuncSetAttribute(flash_tc,
                         cudaFuncAttributeMaxDynamicSharedMemorySize, F_SMEM);

    const int nBig = MM * DMODEL;          // 8,388,608
    const int nW   = DMODEL * DMODEL;      // 1,048,576

    f2h_inputs<<<dim3(nBig / 4 / 256, 1, 3), 256>>>(Q, K, V, hq, hk, hv, nBig);
    f2h_weights<<<dim3(nW / 4 / 256, 1, 4), 256>>>(W_q, W_k, W_v, W_o, hw, nW);

    // fused QKV projections (fp16 out; q pre-scaled by log2e/sqrt(Dk))
    gemm_qkv<<<dim3(DMODEL / 128, MM / 128, 3), 256, G_SMEM>>>(
        hq, hk, hv, hw, b_q, b_k, b_v, pq, pk, pv);

    // tensor-core causal flash attention (BM=128, exp2 softmax)
    flash_tc<<<dim3(SS / 128, BB * HH), 256, F_SMEM>>>(pq, pk, pv, gattn);

    // O projection (fp32 out)
    gemm_hmma<<<dim3(DMODEL / 128, MM / 128), 256, G_SMEM>>>(
        gattn, hw + 3 * (size_t)nW, b_o, out);
}